// round 6
// baseline (speedup 1.0000x reference)
#include <cuda_runtime.h>

// Problem constants
#define BSZ   8192
#define D     256
#define KH    128             // K per thread-half (split-K)
#define H1    50
#define H1P   64
#define H2    32
#define O     18
#define ROWS  64              // rows per block
#define NB2   (BSZ/ROWS)      // 128 blocks -> single wave
#define TPB   1024
#define XS    260             // x smem row stride (floats), 16B-multiple
#define PBC   (O + 1 + O)     // [sum_wu(18), sum_ld(1), sum_y(18)] = 37

// Shared memory layout (floats)
#define OFF_W1  0                        // 256*64 = 16384
#define OFF_X   16384                    // 64*260 = 16640
#define OFF_W2  (OFF_X + ROWS*XS)        // 1600
#define OFF_W3  (OFF_W2 + H1*H2)         // 576
#define OFF_B1  (OFF_W3 + H2*O)          // 64
#define OFF_B2  (OFF_B1 + 64)            // 32
#define OFF_B3  (OFF_B2 + 32)            // 32
#define OFF_H1  (OFF_B3 + 32)            // 64*50 = 3200
#define OFF_H2  (OFF_H1 + ROWS*H1)       // 64*32 = 2048
#define OFF_WU  (OFF_H2 + ROWS*H2)       // 64*18 = 1152
#define OFF_LD  (OFF_WU + ROWS*O)        // 64
#define OFF_Y   (OFF_LD + ROWS)          // 64*18 = 1152
#define OFF_P   (OFF_Y + ROWS*O)         // 64*64 = 4096 split-K partials
#define SMEM_FLOATS (OFF_P + ROWS*H1P)
#define SMEM_BYTES  (SMEM_FLOATS * 4)    // ~188KB

// Deterministic partial-sum scratch + completion counter
__device__ float g_pB[NB2][PBC];
__device__ int   g_count = 0;

__device__ __forceinline__ float sigmoidf(float v) {
    return 1.0f / (1.0f + __expf(-v));
}

// ---------------------------------------------------------------------------
// Single fused kernel
// ---------------------------------------------------------------------------
__global__ __launch_bounds__(TPB, 1) void k_main(
    const float* __restrict__ x,  const float* __restrict__ y,
    const float* __restrict__ W1, const float* __restrict__ b1,
    const float* __restrict__ W2, const float* __restrict__ b2,
    const float* __restrict__ W3, const float* __restrict__ b3,
    float* __restrict__ out)
{
    extern __shared__ float sm[];
    float* sW1 = sm + OFF_W1;
    float* sX  = sm + OFF_X;
    float* sW2 = sm + OFF_W2;
    float* sW3 = sm + OFF_W3;
    float* sb1 = sm + OFF_B1;
    float* sb2 = sm + OFF_B2;
    float* sb3 = sm + OFF_B3;
    float* sH1 = sm + OFF_H1;
    float* sH2 = sm + OFF_H2;
    float* sWU = sm + OFF_WU;
    float* sLD = sm + OFF_LD;
    float* sY  = sm + OFF_Y;
    float* sP  = sm + OFF_P;
    __shared__ int sIsLast;

    const int tid  = threadIdx.x;
    const int row0 = blockIdx.x * ROWS;

    // ---- Stage 0: cooperative staging (vectorized) ----
    {   // x tile row-major float4
        const float4* xg = reinterpret_cast<const float4*>(x + (size_t)row0 * D);
#pragma unroll
        for (int i = tid; i < ROWS * (D / 4); i += TPB) {
            const int r = i >> 6, c = i & 63;
            reinterpret_cast<float4*>(sX + r * XS)[c] = xg[r * 64 + c];
        }
    }
    {   // W1 [256][50] -> padded [256][64], float2 both sides
        const float2* W1v = reinterpret_cast<const float2*>(W1);
        float2* sW1v = reinterpret_cast<float2*>(sW1);
        const float2 z2 = make_float2(0.f, 0.f);
#pragma unroll
        for (int i = tid; i < D * 32; i += TPB) {
            const int k = i >> 5, u2 = i & 31;
            sW1v[i] = (u2 < 25) ? W1v[k * 25 + u2] : z2;
        }
    }
    {   // y tile float2
        const float2* yg = reinterpret_cast<const float2*>(y + (size_t)row0 * O);
        float2* sYv = reinterpret_cast<float2*>(sY);
        for (int i = tid; i < ROWS * O / 2; i += TPB) sYv[i] = yg[i];
    }
    {   // W2, W3 as float2
        const float2* W2v = reinterpret_cast<const float2*>(W2);
        float2* sW2v = reinterpret_cast<float2*>(sW2);
        for (int i = tid; i < H1 * H2 / 2; i += TPB) sW2v[i] = W2v[i];
        const float2* W3v = reinterpret_cast<const float2*>(W3);
        float2* sW3v = reinterpret_cast<float2*>(sW3);
        for (int i = tid; i < H2 * O / 2; i += TPB) sW3v[i] = W3v[i];
    }
    if (tid < H1)                 sb1[tid] = b1[tid];
    else if (tid < H1 + H2)       sb2[tid - H1] = b2[tid - H1];
    else if (tid < H1 + H2 + O)   sb3[tid - H1 - H2] = b3[tid - H1 - H2];
    __syncthreads();

    // ---- Stage 1: layer 1 GEMM, split-K, 2 rows x 4 units per thread ----
    {
        const int kh = tid >> 9;            // K-half: 0 or 1
        const int rg = (tid >> 4) & 31;     // 2-row group
        const int tc = tid & 15;            // unit quad: u0 = 4*tc
        const float* xb = sX + rg * 2 * XS + kh * KH;
        const float* wb = sW1 + kh * KH * H1P + 4 * tc;

        float a[2][4];
#pragma unroll
        for (int r = 0; r < 2; r++)
#pragma unroll
            for (int j = 0; j < 4; j++) a[r][j] = 0.f;

#pragma unroll 4
        for (int k = 0; k < KH; k += 4) {
            float4 xv[2];
#pragma unroll
            for (int r = 0; r < 2; r++)
                xv[r] = *reinterpret_cast<const float4*>(xb + r * XS + k);
            float4 wv[4];
#pragma unroll
            for (int kk = 0; kk < 4; kk++)
                wv[kk] = *reinterpret_cast<const float4*>(wb + (k + kk) * H1P);
#pragma unroll
            for (int r = 0; r < 2; r++) {
                a[r][0] = fmaf(xv[r].x, wv[0].x, a[r][0]);
                a[r][1] = fmaf(xv[r].x, wv[0].y, a[r][1]);
                a[r][2] = fmaf(xv[r].x, wv[0].z, a[r][2]);
                a[r][3] = fmaf(xv[r].x, wv[0].w, a[r][3]);
                a[r][0] = fmaf(xv[r].y, wv[1].x, a[r][0]);
                a[r][1] = fmaf(xv[r].y, wv[1].y, a[r][1]);
                a[r][2] = fmaf(xv[r].y, wv[1].z, a[r][2]);
                a[r][3] = fmaf(xv[r].y, wv[1].w, a[r][3]);
                a[r][0] = fmaf(xv[r].z, wv[2].x, a[r][0]);
                a[r][1] = fmaf(xv[r].z, wv[2].y, a[r][1]);
                a[r][2] = fmaf(xv[r].z, wv[2].z, a[r][2]);
                a[r][3] = fmaf(xv[r].z, wv[2].w, a[r][3]);
                a[r][0] = fmaf(xv[r].w, wv[3].x, a[r][0]);
                a[r][1] = fmaf(xv[r].w, wv[3].y, a[r][1]);
                a[r][2] = fmaf(xv[r].w, wv[3].z, a[r][2]);
                a[r][3] = fmaf(xv[r].w, wv[3].w, a[r][3]);
            }
        }

        // kh=1 writes partials; kh=0 combines, adds bias, sigmoids
        if (kh == 1) {
#pragma unroll
            for (int r = 0; r < 2; r++)
                *reinterpret_cast<float4*>(sP + (rg * 2 + r) * H1P + 4 * tc) =
                    make_float4(a[r][0], a[r][1], a[r][2], a[r][3]);
        }
        __syncthreads();
        if (kh == 0) {
            const int u0 = 4 * tc;
#pragma unroll
            for (int r = 0; r < 2; r++) {
                const float4 p = *reinterpret_cast<const float4*>(
                    sP + (rg * 2 + r) * H1P + u0);
                a[r][0] += p.x; a[r][1] += p.y; a[r][2] += p.z; a[r][3] += p.w;
            }
#pragma unroll
            for (int j = 0; j < 4; j++) {
                const int u = u0 + j;
                if (u < H1) {
                    const float bb = sb1[u];
#pragma unroll
                    for (int r = 0; r < 2; r++)
                        sH1[(rg * 2 + r) * H1 + u] = sigmoidf(a[r][j] + bb);
                }
            }
        }
    }
    __syncthreads();

    // ---- Stage 2: layer 2 (64 rows x 32 units, K=50), float2 over k ----
    {
        const int u  = tid & 31;
        const int rg = tid >> 5;   // 0..31, rows rg, rg+32
        float acc0 = sb2[u], acc1 = acc0;
#pragma unroll
        for (int k = 0; k < H1; k += 2) {
            const float w0 = sW2[k * H2 + u];
            const float w1 = sW2[(k + 1) * H2 + u];
            const float2 h0 = *reinterpret_cast<const float2*>(sH1 + rg * H1 + k);
            const float2 h1 = *reinterpret_cast<const float2*>(sH1 + (rg + 32) * H1 + k);
            acc0 = fmaf(h0.x, w0, fmaf(h0.y, w1, acc0));
            acc1 = fmaf(h1.x, w0, fmaf(h1.y, w1, acc1));
        }
        sH2[rg * H2 + u]        = sigmoidf(acc0);
        sH2[(rg + 32) * H2 + u] = sigmoidf(acc1);
    }
    __syncthreads();

    // ---- Stage 3: layer 3 (64 rows x 18 units, K=32) + store W_user ----
    {
        const int w = tid >> 5, l = tid & 31;   // 32 warps x 2 rows
        if (l < O) {
#pragma unroll
            for (int rr = 0; rr < 2; rr++) {
                const int r = w * 2 + rr;
                float a = sb3[l];
#pragma unroll
                for (int k = 0; k < H2; k++)
                    a = fmaf(sH2[r * H2 + k], sW3[k * O + l], a);
                sWU[r * O + l] = a;
                out[(size_t)(row0 + r) * O + l] = a;
            }
        }
    }
    __syncthreads();

    // ---- Stage 4: factorized log-denominator per row ----
    if (tid < ROWS) {
        const float* wu = sWU + tid * O;
        float ld = 0.f;
        {
            const float m = fmaxf(wu[0], wu[1]);
            ld += m + __logf(__expf(wu[0] - m) + __expf(wu[1] - m));
        }
        {
            const float m = fmaxf(fmaxf(wu[2], wu[3]), fmaxf(wu[4], wu[5]));
            ld += m + __logf(__expf(wu[2] - m) + __expf(wu[3] - m) +
                             __expf(wu[4] - m) + __expf(wu[5] - m));
        }
        {
            const float m = fmaxf(fmaxf(wu[6], wu[7]), fmaxf(wu[8], wu[9]));
            ld += m + __logf(__expf(wu[6] - m) + __expf(wu[7] - m) +
                             __expf(wu[8] - m) + __expf(wu[9] - m));
        }
        {
            float m = wu[10];
#pragma unroll
            for (int j = 11; j < 18; j++) m = fmaxf(m, wu[j]);
            float s = 0.f;
#pragma unroll
            for (int j = 10; j < 18; j++) s += __expf(wu[j] - m);
            ld += m + __logf(s);
        }
        sLD[tid] = ld;
    }
    __syncthreads();

    // ---- Stage 5: deterministic block partials (L2-resident) ----
    if (tid < O) {
        float s = 0.f;
#pragma unroll
        for (int r = 0; r < ROWS; r++) s += sWU[r * O + tid];
        __stcg(&g_pB[blockIdx.x][tid], s);
    } else if (tid == O) {
        float s = 0.f;
#pragma unroll
        for (int r = 0; r < ROWS; r++) s += sLD[r];
        __stcg(&g_pB[blockIdx.x][O], s);
    } else if (tid >= 32 && tid < 32 + O) {
        const int j = tid - 32;
        float s = 0.f;
#pragma unroll
        for (int r = 0; r < ROWS; r++) s += sY[r * O + j];
        __stcg(&g_pB[blockIdx.x][O + 1 + j], s);
    }

    // ---- Stage 6: last-block final combine ----
    __threadfence();
    __syncthreads();
    if (tid == 0) {
        const int old = atomicAdd(&g_count, 1);
        sIsLast = (old == NB2 - 1);
    }
    __syncthreads();
    if (!sIsLast) return;
    __threadfence();   // acquire all blocks' g_pB stores

    {
        float* part = sm;            // [8][PBC]
        float* tot  = sm + 8 * PBC;  // [PBC]
        const int j   = tid & 63;
        const int seg = tid >> 6;    // use first 8 segments x 16 blocks
        if (seg < 8 && j < PBC) {
            float s = 0.f;
            const int b0 = seg * (NB2 / 8);
#pragma unroll
            for (int b = 0; b < NB2 / 8; b++)
                s += __ldcg(&g_pB[b0 + b][j]);
            part[seg * PBC + j] = s;
        }
        __syncthreads();
        if (tid < PBC) {
            float s = 0.f;
#pragma unroll
            for (int sg = 0; sg < 8; sg++) s += part[sg * PBC + tid];
            tot[tid] = s;
        }
        __syncthreads();
        if (tid == 0) {
            float dot = 0.f;
#pragma unroll
            for (int jj = 0; jj < O; jj++) dot += tot[jj] * tot[O + 1 + jj];
            out[(size_t)BSZ * O] = -(dot - tot[O]);
            g_count = 0;   // reset for graph replay
        }
    }
}

// ---------------------------------------------------------------------------
extern "C" void kernel_launch(void* const* d_in, const int* in_sizes, int n_in,
                              void* d_out, int out_size) {
    const float* x  = (const float*)d_in[0];
    const float* y  = (const float*)d_in[1];
    const float* W1 = (const float*)d_in[2];
    const float* b1 = (const float*)d_in[3];
    const float* W2 = (const float*)d_in[4];
    const float* b2 = (const float*)d_in[5];
    const float* W3 = (const float*)d_in[6];
    const float* b3 = (const float*)d_in[7];
    float* out = (float*)d_out;

    cudaFuncSetAttribute(k_main, cudaFuncAttributeMaxDynamicSharedMemorySize,
                         SMEM_BYTES);

    k_main<<<NB2, TPB, SMEM_BYTES>>>(x, y, W1, b1, W2, b2, W3, b3, out);
}

// round 8
// speedup vs baseline: 1.3183x; 1.3183x over previous
#include <cuda_runtime.h>
#include <cuda_bf16.h>
#include <cstdint>

// Problem constants
#define BSZ   8192
#define D     256
#define H1    50
#define H1S   52              // sH1 row stride (floats)
#define H2    32
#define O     18
#define ROWS  64              // rows per block = MMA M tile
#define NBLK  (BSZ/ROWS)      // 128 blocks -> single wave
#define TPB   512
#define NPAD  64              // padded layer-1 units = MMA N tile
#define BS    264             // bf16 smem row stride (528B, ldmatrix conflict-free)
#define PBC   (O + 1 + O)     // [sum_wu(18), sum_ld(1), sum_y(18)] = 37

// ---- SMEM byte layout ----
#define XHI    0                       // 64 x 264 bf16 = 33792
#define XLO    33792
#define WHI    67584                   // 64(units) x 264 bf16
#define WLO    101376
#define OFF_W2 135168                  // 1600 f
#define OFF_W3 141568                  // 576 f
#define OFF_B1 143872                  // 64 f
#define OFF_B2 144128
#define OFF_B3 144384
#define OFF_H1 144640                  // 64 x 52 f = 13312 B
#define OFF_H2 157952                  // 64 x 32 f = 8192 B
#define OFF_WU 166144                  // 64 x 18 f = 4608 B
#define OFF_Y  170752                  // 4608 B
#define OFF_LD 175360                  // 256 B
#define OFF_FL 175616                  // 4 B
#define SMEM_BYTES 175620

// Deterministic partial-sum scratch + completion counter
__device__ float g_pB[NBLK][PBC];
__device__ int   g_count = 0;

__device__ __forceinline__ float sigmoidf(float v) {
    return 1.0f / (1.0f + __expf(-v));
}
__device__ __forceinline__ uint32_t smem_u32(const void* p) {
    uint32_t a;
    asm("{ .reg .u64 t; cvta.to.shared.u64 t, %1; cvt.u32.u64 %0, t; }"
        : "=r"(a) : "l"(p));
    return a;
}
__device__ __forceinline__ void split_bf16(float v, uint16_t& hi, uint16_t& lo) {
    __nv_bfloat16 h = __float2bfloat16(v);
    float r = v - __bfloat162float(h);
    __nv_bfloat16 l = __float2bfloat16(r);
    hi = *reinterpret_cast<uint16_t*>(&h);
    lo = *reinterpret_cast<uint16_t*>(&l);
}
__device__ __forceinline__ void ldm_x4(uint32_t a[4], uint32_t addr) {
    asm volatile("ldmatrix.sync.aligned.m8n8.x4.shared.b16 {%0,%1,%2,%3}, [%4];"
                 : "=r"(a[0]), "=r"(a[1]), "=r"(a[2]), "=r"(a[3]) : "r"(addr));
}
__device__ __forceinline__ void ldm_x2(uint32_t b[2], uint32_t addr) {
    asm volatile("ldmatrix.sync.aligned.m8n8.x2.shared.b16 {%0,%1}, [%2];"
                 : "=r"(b[0]), "=r"(b[1]) : "r"(addr));
}
__device__ __forceinline__ void mma_bf16(float c[4], const uint32_t a[4],
                                         const uint32_t b[2]) {
    asm volatile(
        "mma.sync.aligned.m16n8k16.row.col.f32.bf16.bf16.f32 "
        "{%0,%1,%2,%3}, {%4,%5,%6,%7}, {%8,%9}, {%0,%1,%2,%3};"
        : "+f"(c[0]), "+f"(c[1]), "+f"(c[2]), "+f"(c[3])
        : "r"(a[0]), "r"(a[1]), "r"(a[2]), "r"(a[3]), "r"(b[0]), "r"(b[1]));
}

// ---------------------------------------------------------------------------
__global__ __launch_bounds__(TPB, 1) void k_main(
    const float* __restrict__ x,  const float* __restrict__ y,
    const float* __restrict__ W1, const float* __restrict__ b1,
    const float* __restrict__ W2, const float* __restrict__ b2,
    const float* __restrict__ W3, const float* __restrict__ b3,
    float* __restrict__ out)
{
    extern __shared__ float sm[];
    char* smb = reinterpret_cast<char*>(sm);
    float* sW2 = reinterpret_cast<float*>(smb + OFF_W2);
    float* sW3 = reinterpret_cast<float*>(smb + OFF_W3);
    float* sb1 = reinterpret_cast<float*>(smb + OFF_B1);
    float* sb2 = reinterpret_cast<float*>(smb + OFF_B2);
    float* sb3 = reinterpret_cast<float*>(smb + OFF_B3);
    float* sH1 = reinterpret_cast<float*>(smb + OFF_H1);
    float* sH2 = reinterpret_cast<float*>(smb + OFF_H2);
    float* sWU = reinterpret_cast<float*>(smb + OFF_WU);
    float* sY  = reinterpret_cast<float*>(smb + OFF_Y);
    float* sLD = reinterpret_cast<float*>(smb + OFF_LD);
    int*   sFlag = reinterpret_cast<int*>(smb + OFF_FL);

    const int tid  = threadIdx.x;
    const int wid  = tid >> 5;
    const int lane = tid & 31;
    const int row0 = blockIdx.x * ROWS;
    const uint32_t sbase = smem_u32(smb);

    // ---- Stage 0: x -> Xhi/Xlo (bf16 split, row-major stride 264) ----
    {
        const float4* xg = reinterpret_cast<const float4*>(x + (size_t)row0 * D);
#pragma unroll
        for (int i = tid; i < ROWS * (D / 4); i += TPB) {
            const uint32_t r = (uint32_t)i >> 6, c4 = (uint32_t)i & 63;
            const float4 v = xg[r * 64 + c4];
            uint16_t h0, l0, h1_, l1_, h2_, l2_, h3, l3;
            split_bf16(v.x, h0, l0); split_bf16(v.y, h1_, l1_);
            split_bf16(v.z, h2_, l2_); split_bf16(v.w, h3, l3);
            const uint32_t byo = (r * BS + c4 * 4) * 2;
            *reinterpret_cast<uint2*>(smb + XHI + byo) =
                make_uint2((uint32_t)h0 | ((uint32_t)h1_ << 16),
                           (uint32_t)h2_ | ((uint32_t)h3 << 16));
            *reinterpret_cast<uint2*>(smb + XLO + byo) =
                make_uint2((uint32_t)l0 | ((uint32_t)l1_ << 16),
                           (uint32_t)l2_ | ((uint32_t)l3 << 16));
        }
    }
    // ---- W1 transpose -> Whi/Wlo [64 units][264 k], units 50-63 zeroed ----
#pragma unroll
    for (int i = tid; i < NPAD * (D / 2); i += TPB) {
        const uint32_t u = (uint32_t)i >> 7, k2 = (uint32_t)i & 127;
        uint16_t h0 = 0, l0 = 0, h1_ = 0, l1_ = 0;
        if (u < H1) {
            split_bf16(W1[(2 * k2) * H1 + u], h0, l0);
            split_bf16(W1[(2 * k2 + 1) * H1 + u], h1_, l1_);
        }
        const uint32_t byo = (u * BS + k2 * 2) * 2;
        *reinterpret_cast<uint32_t*>(smb + WHI + byo) =
            (uint32_t)h0 | ((uint32_t)h1_ << 16);
        *reinterpret_cast<uint32_t*>(smb + WLO + byo) =
            (uint32_t)l0 | ((uint32_t)l1_ << 16);
    }
    // ---- small tensors ----
    {
        const float2* yg = reinterpret_cast<const float2*>(y + (size_t)row0 * O);
        float2* sYv = reinterpret_cast<float2*>(sY);
        for (int i = tid; i < ROWS * O / 2; i += TPB) sYv[i] = yg[i];
        const float2* W2v = reinterpret_cast<const float2*>(W2);
        float2* sW2v = reinterpret_cast<float2*>(sW2);
        for (int i = tid; i < H1 * H2 / 2; i += TPB) sW2v[i] = W2v[i];
        const float2* W3v = reinterpret_cast<const float2*>(W3);
        float2* sW3v = reinterpret_cast<float2*>(sW3);
        for (int i = tid; i < H2 * O / 2; i += TPB) sW3v[i] = W3v[i];
        if (tid < H1)                 sb1[tid] = b1[tid];
        else if (tid < H1 + H2)       sb2[tid - H1] = b2[tid - H1];
        else if (tid < H1 + H2 + O)   sb3[tid - H1 - H2] = b3[tid - H1 - H2];
    }
    __syncthreads();

    // ---- Layer 1: tensor-core GEMM, warp tile 16m x 16n, 3-term bf16 ----
    {
        const int m0 = (wid & 3) * 16;      // 4 m-groups
        const int n0 = (wid >> 2) * 16;     // 4 n-groups
        // ldmatrix lane addressing
        const uint32_t arow = m0 + (lane & 15);
        const uint32_t acol = (lane >> 4) * 8;
        const uint32_t aoff = (arow * BS + acol) * 2;
        const uint32_t brow = (lane & 7);
        const uint32_t bcol = ((lane >> 3) & 1) * 8;

        float c0[4] = {0.f, 0.f, 0.f, 0.f};   // n-tile 0 (cols n0..n0+7)
        float c1[4] = {0.f, 0.f, 0.f, 0.f};   // n-tile 1 (cols n0+8..n0+15)

#pragma unroll
        for (int k0 = 0; k0 < D; k0 += 16) {
            uint32_t ah[4], al[4], bh0[2], bl0[2], bh1[2], bl1[2];
            const uint32_t ka = (uint32_t)k0 * 2;
            ldm_x4(ah, sbase + XHI + aoff + ka);
            ldm_x4(al, sbase + XLO + aoff + ka);
            const uint32_t bo0 = ((n0 + brow) * BS + k0 + bcol) * 2;
            const uint32_t bo1 = ((n0 + 8 + brow) * BS + k0 + bcol) * 2;
            ldm_x2(bh0, sbase + WHI + bo0);
            ldm_x2(bl0, sbase + WLO + bo0);
            ldm_x2(bh1, sbase + WHI + bo1);
            ldm_x2(bl1, sbase + WLO + bo1);
            mma_bf16(c0, ah, bh0);
            mma_bf16(c1, ah, bh1);
            mma_bf16(c0, ah, bl0);
            mma_bf16(c1, ah, bl1);
            mma_bf16(c0, al, bh0);
            mma_bf16(c1, al, bh1);
        }

        // write h1 = sigmoid(acc + b1) straight from fragments
        const int r0 = m0 + (lane >> 2);
#pragma unroll
        for (int nt = 0; nt < 2; nt++) {
            const int col = n0 + nt * 8 + (lane & 3) * 2;
            if (col < H1) {     // col even, col+1 <= 49
                const float bb0 = sb1[col], bb1 = sb1[col + 1];
                const float* c = nt ? c1 : c0;
                *reinterpret_cast<float2*>(sH1 + r0 * H1S + col) =
                    make_float2(sigmoidf(c[0] + bb0), sigmoidf(c[1] + bb1));
                *reinterpret_cast<float2*>(sH1 + (r0 + 8) * H1S + col) =
                    make_float2(sigmoidf(c[2] + bb0), sigmoidf(c[3] + bb1));
            }
        }
    }
    __syncthreads();

    // ---- Layer 2 (64 rows x 32 units, K=50) ----
    {
        const int u  = tid & 31;
        const int rg = tid >> 5;   // 0..15, rows rg + 16*s
        float acc[4];
#pragma unroll
        for (int s = 0; s < 4; s++) acc[s] = sb2[u];
#pragma unroll
        for (int k = 0; k < H1; k += 2) {
            const float w0 = sW2[k * H2 + u];
            const float w1 = sW2[(k + 1) * H2 + u];
#pragma unroll
            for (int s = 0; s < 4; s++) {
                const float2 h = *reinterpret_cast<const float2*>(
                    sH1 + (rg + 16 * s) * H1S + k);
                acc[s] = fmaf(h.x, w0, fmaf(h.y, w1, acc[s]));
            }
        }
#pragma unroll
        for (int s = 0; s < 4; s++)
            sH2[(rg + 16 * s) * H2 + u] = sigmoidf(acc[s]);
    }
    __syncthreads();

    // ---- Layer 3 (64 rows x 18, K=32) -> sWU ----
    {
        const int w = tid >> 5, l = tid & 31;   // 16 warps x 4 rows
        if (l < O) {
#pragma unroll
            for (int rr = 0; rr < 4; rr++) {
                const int r = w * 4 + rr;
                float a = sb3[l];
#pragma unroll
                for (int k = 0; k < H2; k++)
                    a = fmaf(sH2[r * H2 + k], sW3[k * O + l], a);
                sWU[r * O + l] = a;
            }
        }
    }
    __syncthreads();

    // ---- factorized log-denominator per row ----
    if (tid < ROWS) {
        const float* wu = sWU + tid * O;
        float ld = 0.f;
        {
            const float m = fmaxf(wu[0], wu[1]);
            ld += m + __logf(__expf(wu[0] - m) + __expf(wu[1] - m));
        }
        {
            const float m = fmaxf(fmaxf(wu[2], wu[3]), fmaxf(wu[4], wu[5]));
            ld += m + __logf(__expf(wu[2] - m) + __expf(wu[3] - m) +
                             __expf(wu[4] - m) + __expf(wu[5] - m));
        }
        {
            const float m = fmaxf(fmaxf(wu[6], wu[7]), fmaxf(wu[8], wu[9]));
            ld += m + __logf(__expf(wu[6] - m) + __expf(wu[7] - m) +
                             __expf(wu[8] - m) + __expf(wu[9] - m));
        }
        {
            float m = wu[10];
#pragma unroll
            for (int j = 11; j < 18; j++) m = fmaxf(m, wu[j]);
            float s = 0.f;
#pragma unroll
            for (int j = 10; j < 18; j++) s += __expf(wu[j] - m);
            ld += m + __logf(s);
        }
        sLD[tid] = ld;
    }
    __syncthreads();

    // ---- coalesced W_user store (1152 floats = 288 float4) ----
    {
        float4* og = reinterpret_cast<float4*>(out + (size_t)row0 * O);
        const float4* wv = reinterpret_cast<const float4*>(sWU);
#pragma unroll
        for (int i = tid; i < ROWS * O / 4; i += TPB) og[i] = wv[i];
    }

    // ---- deterministic block partials (L2-resident) ----
    if (tid < O) {
        float s = 0.f;
#pragma unroll
        for (int r = 0; r < ROWS; r++) s += sWU[r * O + tid];
        __stcg(&g_pB[blockIdx.x][tid], s);
    } else if (tid == O) {
        float s = 0.f;
#pragma unroll
        for (int r = 0; r < ROWS; r++) s += sLD[r];
        __stcg(&g_pB[blockIdx.x][O], s);
    } else if (tid >= 32 && tid < 32 + O) {
        const int j = tid - 32;
        float s = 0.f;
#pragma unroll
        for (int r = 0; r < ROWS; r++) s += sY[r * O + j];
        __stcg(&g_pB[blockIdx.x][O + 1 + j], s);
    }

    // ---- last-block final combine ----
    __threadfence();
    __syncthreads();
    if (tid == 0) {
        const int old = atomicAdd(&g_count, 1);
        *sFlag = (old == NBLK - 1);
    }
    __syncthreads();
    if (!*sFlag) return;
    __threadfence();   // acquire all blocks' g_pB stores

    {
        float* part = sm;            // [8][PBC]
        float* tot  = sm + 8 * PBC;  // [PBC]
        const int j   = tid & 63;
        const int seg = tid >> 6;    // 8 segments x 16 blocks
        if (j < PBC) {
            float s = 0.f;
#pragma unroll
            for (int b = 0; b < NBLK / 8; b++)
                s += __ldcg(&g_pB[seg * (NBLK / 8) + b][j]);
            part[seg * PBC + j] = s;
        }
        __syncthreads();
        if (tid < PBC) {
            float s = 0.f;
#pragma unroll
            for (int sg = 0; sg < 8; sg++) s += part[sg * PBC + tid];
            tot[tid] = s;
        }
        __syncthreads();
        if (tid == 0) {
            float dot = 0.f;
#pragma unroll
            for (int jj = 0; jj < O; jj++) dot += tot[jj] * tot[O + 1 + jj];
            out[(size_t)BSZ * O] = -(dot - tot[O]);
            g_count = 0;   // reset for graph replay
        }
    }
}

// ---------------------------------------------------------------------------
extern "C" void kernel_launch(void* const* d_in, const int* in_sizes, int n_in,
                              void* d_out, int out_size) {
    const float* x  = (const float*)d_in[0];
    const float* y  = (const float*)d_in[1];
    const float* W1 = (const float*)d_in[2];
    const float* b1 = (const float*)d_in[3];
    const float* W2 = (const float*)d_in[4];
    const float* b2 = (const float*)d_in[5];
    const float* W3 = (const float*)d_in[6];
    const float* b3 = (const float*)d_in[7];
    float* out = (float*)d_out;

    cudaFuncSetAttribute(k_main, cudaFuncAttributeMaxDynamicSharedMemorySize,
                         SMEM_BYTES);

    k_main<<<NBLK, TPB, SMEM_BYTES>>>(x, y, W1, b1, W2, b2, W3, b3, out);
}

// round 9
// speedup vs baseline: 1.3384x; 1.0152x over previous
#include <cuda_runtime.h>
#include <cuda_bf16.h>
#include <cstdint>

// Problem constants
#define BSZ   8192
#define D     256
#define H1    50
#define H1S   52              // sH1 row stride (floats)
#define H2    32
#define O     18
#define ROWS  32              // rows per block = MMA M tile
#define NBLK  (BSZ/ROWS)      // 256 blocks -> 2 CTAs/SM coresident
#define TPB   256
#define BS    264             // x smem row stride in bf16 (528B, conflict-free)
#define PBC   (O + 1 + O)     // 37 partial columns

// ---- SMEM byte layout (total 110992 <= 113.5KB for 2 CTAs/SM) ----
#define XHI    0               // 32 x 264 bf16 = 16896
#define XLO    16896           // 16896 (reused post-MMA for H1/H2/WU)
#define WHI    33792           // 256 x 64 bf16 k-major SW128 = 32768
#define WLO    66560           // 32768
#define OFF_W2 99328           // 6400
#define OFF_W3 105728          // 2304
#define OFF_B1 108032          // 256
#define OFF_B2 108288          // 128
#define OFF_B3 108416          // 128
#define OFF_Y  108544          // 2304
#define OFF_LD 110848          // 128
#define OFF_FL 110976          // 16
#define SMEM_BYTES 110992
// post-MMA reuse of XLO:
#define OFF_H1 XLO             // 32 x 52 f = 6656
#define OFF_H2 (XLO + 6656)    // 32 x 32 f = 4096
#define OFF_WU (XLO + 10752)   // 32 x 18 f = 2304

// Deterministic partial-sum scratch + completion counter
__device__ float g_pB[NBLK][PBC];
__device__ int   g_count = 0;

__device__ __forceinline__ float sigmoidf(float v) {
    return 1.0f / (1.0f + __expf(-v));
}
__device__ __forceinline__ uint32_t smem_u32(const void* p) {
    uint32_t a;
    asm("{ .reg .u64 t; cvta.to.shared.u64 t, %1; cvt.u32.u64 %0, t; }"
        : "=r"(a) : "l"(p));
    return a;
}
__device__ __forceinline__ void split_bf16(float v, uint16_t& hi, uint16_t& lo) {
    __nv_bfloat16 h = __float2bfloat16(v);
    float r = v - __bfloat162float(h);
    __nv_bfloat16 l = __float2bfloat16(r);
    hi = *reinterpret_cast<uint16_t*>(&h);
    lo = *reinterpret_cast<uint16_t*>(&l);
}
__device__ __forceinline__ void ldm_x4(uint32_t a[4], uint32_t addr) {
    asm volatile("ldmatrix.sync.aligned.m8n8.x4.shared.b16 {%0,%1,%2,%3}, [%4];"
                 : "=r"(a[0]), "=r"(a[1]), "=r"(a[2]), "=r"(a[3]) : "r"(addr));
}
__device__ __forceinline__ void ldm_x2t(uint32_t b[2], uint32_t addr) {
    asm volatile("ldmatrix.sync.aligned.m8n8.x2.trans.shared.b16 {%0,%1}, [%2];"
                 : "=r"(b[0]), "=r"(b[1]) : "r"(addr));
}
__device__ __forceinline__ void mma_bf16(float c[4], const uint32_t a[4],
                                         const uint32_t b[2]) {
    asm volatile(
        "mma.sync.aligned.m16n8k16.row.col.f32.bf16.bf16.f32 "
        "{%0,%1,%2,%3}, {%4,%5,%6,%7}, {%8,%9}, {%0,%1,%2,%3};"
        : "+f"(c[0]), "+f"(c[1]), "+f"(c[2]), "+f"(c[3])
        : "r"(a[0]), "r"(a[1]), "r"(a[2]), "r"(a[3]), "r"(b[0]), "r"(b[1]));
}

// ---------------------------------------------------------------------------
__global__ __launch_bounds__(TPB, 2) void k_main(
    const float* __restrict__ x,  const float* __restrict__ y,
    const float* __restrict__ W1, const float* __restrict__ b1,
    const float* __restrict__ W2, const float* __restrict__ b2,
    const float* __restrict__ W3, const float* __restrict__ b3,
    float* __restrict__ out)
{
    extern __shared__ float sm[];
    char* smb = reinterpret_cast<char*>(sm);
    float* sW2 = reinterpret_cast<float*>(smb + OFF_W2);
    float* sW3 = reinterpret_cast<float*>(smb + OFF_W3);
    float* sb1 = reinterpret_cast<float*>(smb + OFF_B1);
    float* sb2 = reinterpret_cast<float*>(smb + OFF_B2);
    float* sb3 = reinterpret_cast<float*>(smb + OFF_B3);
    float* sH1 = reinterpret_cast<float*>(smb + OFF_H1);
    float* sH2 = reinterpret_cast<float*>(smb + OFF_H2);
    float* sWU = reinterpret_cast<float*>(smb + OFF_WU);
    float* sY  = reinterpret_cast<float*>(smb + OFF_Y);
    float* sLD = reinterpret_cast<float*>(smb + OFF_LD);
    int*   sFlag = reinterpret_cast<int*>(smb + OFF_FL);

    const int tid  = threadIdx.x;
    const int wid  = tid >> 5;
    const int lane = tid & 31;
    const int row0 = blockIdx.x * ROWS;
    const uint32_t sbase = smem_u32(smb);

    // ---- Stage 0a: x -> Xhi/Xlo (bf16 split, row-major stride 264) ----
    {
        const float4* xg = reinterpret_cast<const float4*>(x + (size_t)row0 * D);
#pragma unroll
        for (int i = tid; i < ROWS * (D / 4); i += TPB) {
            const uint32_t r = (uint32_t)i >> 6, c4 = (uint32_t)i & 63;
            const float4 v = xg[r * 64 + c4];
            uint16_t h0, l0, h1_, l1_, h2_, l2_, h3, l3;
            split_bf16(v.x, h0, l0); split_bf16(v.y, h1_, l1_);
            split_bf16(v.z, h2_, l2_); split_bf16(v.w, h3, l3);
            const uint32_t byo = (r * BS + c4 * 4) * 2;
            *reinterpret_cast<uint2*>(smb + XHI + byo) =
                make_uint2((uint32_t)h0 | ((uint32_t)h1_ << 16),
                           (uint32_t)h2_ | ((uint32_t)h3 << 16));
            *reinterpret_cast<uint2*>(smb + XLO + byo) =
                make_uint2((uint32_t)l0 | ((uint32_t)l1_ << 16),
                           (uint32_t)l2_ | ((uint32_t)l3 << 16));
        }
    }
    // ---- Stage 0b: W1 k-major -> Whi/Wlo [256 k][64 u] SW128-swizzled ----
    // coalesced float2 gmem reads; units 50-63 zero
    {
        const float2* W1v = reinterpret_cast<const float2*>(W1);
#pragma unroll
        for (int i = tid; i < D * 32; i += TPB) {
            const uint32_t k = (uint32_t)i >> 5, u2 = (uint32_t)i & 31;
            uint16_t h0 = 0, l0 = 0, h1_ = 0, l1_ = 0;
            if (u2 < 25) {
                const float2 w = W1v[k * 25 + u2];
                split_bf16(w.x, h0, l0);
                split_bf16(w.y, h1_, l1_);
            }
            // swizzled byte offset within 128B row
            const uint32_t o = k * 128 + ((u2 * 4) ^ ((k & 7) << 4));
            *reinterpret_cast<uint32_t*>(smb + WHI + o) =
                (uint32_t)h0 | ((uint32_t)h1_ << 16);
            *reinterpret_cast<uint32_t*>(smb + WLO + o) =
                (uint32_t)l0 | ((uint32_t)l1_ << 16);
        }
    }
    // ---- small tensors ----
    {
        const float2* yg = reinterpret_cast<const float2*>(y + (size_t)row0 * O);
        float2* sYv = reinterpret_cast<float2*>(sY);
        for (int i = tid; i < ROWS * O / 2; i += TPB) sYv[i] = yg[i];
        const float2* W2v = reinterpret_cast<const float2*>(W2);
        float2* sW2v = reinterpret_cast<float2*>(sW2);
        for (int i = tid; i < H1 * H2 / 2; i += TPB) sW2v[i] = W2v[i];
        const float2* W3v = reinterpret_cast<const float2*>(W3);
        float2* sW3v = reinterpret_cast<float2*>(sW3);
        for (int i = tid; i < H2 * O / 2; i += TPB) sW3v[i] = W3v[i];
        if (tid < H1)                 sb1[tid] = b1[tid];
        else if (tid < H1 + H2)       sb2[tid - H1] = b2[tid - H1];
        else if (tid < H1 + H2 + O)   sb3[tid - H1 - H2] = b3[tid - H1 - H2];
    }
    __syncthreads();

    // ---- Layer 1: tensor-core GEMM, warp tile 16m x 16n, 3-term bf16 ----
    // 8 warps: 2 m-groups x 4 n-groups
    float c0[4] = {0.f, 0.f, 0.f, 0.f};
    float c1[4] = {0.f, 0.f, 0.f, 0.f};
    int m0, n0;
    {
        m0 = (wid & 1) * 16;
        n0 = (wid >> 1) * 16;
        // A (row-major, padded): lanes 0-15 rows, 16-31 k+8
        const uint32_t arow = m0 + (lane & 15);
        const uint32_t acol = (lane >> 4) * 8;
        const uint32_t aoff = (arow * BS + acol) * 2;
        // B (k-major swizzled, trans): lane l -> row k0+l, col n0
        const uint32_t bl = lane & 15;
        const uint32_t bxor = (bl & 7) << 4;
        // base addresses at k0=0 (row term advances by 16*128 per k-step)
        uint32_t b0addr = WHI + bl * 128 + ((n0 * 2) ^ bxor);
        uint32_t b1addr = WHI + bl * 128 + (((n0 + 8) * 2) ^ bxor);
        const uint32_t dLO = WLO - WHI;

#pragma unroll
        for (int k0 = 0; k0 < D; k0 += 16) {
            uint32_t ah[4], al[4], bh0[2], bl0[2], bh1[2], bl1[2];
            const uint32_t ka = (uint32_t)k0 * 2;
            ldm_x4(ah, sbase + XHI + aoff + ka);
            ldm_x4(al, sbase + XLO + aoff + ka);
            ldm_x2t(bh0, sbase + b0addr);
            ldm_x2t(bl0, sbase + b0addr + dLO);
            ldm_x2t(bh1, sbase + b1addr);
            ldm_x2t(bl1, sbase + b1addr + dLO);
            mma_bf16(c0, ah, bh0);
            mma_bf16(c1, ah, bh1);
            mma_bf16(c0, ah, bl0);
            mma_bf16(c1, ah, bl1);
            mma_bf16(c0, al, bh0);
            mma_bf16(c1, al, bh1);
            b0addr += 16 * 128;
            b1addr += 16 * 128;
        }
    }
    // all XLO reads done in-warp; barrier before reusing XLO as sH1
    __syncthreads();

    // write h1 = sigmoid(acc + b1) from fragments
    {
        const int r0 = m0 + (lane >> 2);
#pragma unroll
        for (int nt = 0; nt < 2; nt++) {
            const int col = n0 + nt * 8 + (lane & 3) * 2;
            if (col < H1) {     // col even, col+1 <= 49
                const float bb0 = sb1[col], bb1 = sb1[col + 1];
                const float* c = nt ? c1 : c0;
                *reinterpret_cast<float2*>(sH1 + r0 * H1S + col) =
                    make_float2(sigmoidf(c[0] + bb0), sigmoidf(c[1] + bb1));
                *reinterpret_cast<float2*>(sH1 + (r0 + 8) * H1S + col) =
                    make_float2(sigmoidf(c[2] + bb0), sigmoidf(c[3] + bb1));
            }
        }
    }
    __syncthreads();

    // ---- Layer 2 (32 rows x 32 units, K=50) ----
    {
        const int u  = tid & 31;
        const int rg = tid >> 5;   // 0..7, rows rg + 8*s
        float acc[4];
#pragma unroll
        for (int s = 0; s < 4; s++) acc[s] = sb2[u];
#pragma unroll
        for (int k = 0; k < H1; k += 2) {
            const float w0 = sW2[k * H2 + u];
            const float w1 = sW2[(k + 1) * H2 + u];
#pragma unroll
            for (int s = 0; s < 4; s++) {
                const float2 h = *reinterpret_cast<const float2*>(
                    sH1 + (rg + 8 * s) * H1S + k);
                acc[s] = fmaf(h.x, w0, fmaf(h.y, w1, acc[s]));
            }
        }
#pragma unroll
        for (int s = 0; s < 4; s++)
            sH2[(rg + 8 * s) * H2 + u] = sigmoidf(acc[s]);
    }
    __syncthreads();

    // ---- Layer 3 (32 rows x 18, K=32) -> sWU ----
    {
        const int w = tid >> 5, l = tid & 31;   // 8 warps x 4 rows
        if (l < O) {
#pragma unroll
            for (int rr = 0; rr < 4; rr++) {
                const int r = w * 4 + rr;
                float a = sb3[l];
#pragma unroll
                for (int k = 0; k < H2; k++)
                    a = fmaf(sH2[r * H2 + k], sW3[k * O + l], a);
                sWU[r * O + l] = a;
            }
        }
    }
    __syncthreads();

    // ---- factorized log-denominator per row ----
    if (tid < ROWS) {
        const float* wu = sWU + tid * O;
        float ld = 0.f;
        {
            const float m = fmaxf(wu[0], wu[1]);
            ld += m + __logf(__expf(wu[0] - m) + __expf(wu[1] - m));
        }
        {
            const float m = fmaxf(fmaxf(wu[2], wu[3]), fmaxf(wu[4], wu[5]));
            ld += m + __logf(__expf(wu[2] - m) + __expf(wu[3] - m) +
                             __expf(wu[4] - m) + __expf(wu[5] - m));
        }
        {
            const float m = fmaxf(fmaxf(wu[6], wu[7]), fmaxf(wu[8], wu[9]));
            ld += m + __logf(__expf(wu[6] - m) + __expf(wu[7] - m) +
                             __expf(wu[8] - m) + __expf(wu[9] - m));
        }
        {
            float m = wu[10];
#pragma unroll
            for (int j = 11; j < 18; j++) m = fmaxf(m, wu[j]);
            float s = 0.f;
#pragma unroll
            for (int j = 10; j < 18; j++) s += __expf(wu[j] - m);
            ld += m + __logf(s);
        }
        sLD[tid] = ld;
    }
    __syncthreads();

    // ---- coalesced W_user store (576 floats = 144 float4) ----
    {
        float4* og = reinterpret_cast<float4*>(out + (size_t)row0 * O);
        const float4* wv = reinterpret_cast<const float4*>(sWU);
#pragma unroll
        for (int i = tid; i < ROWS * O / 4; i += TPB) og[i] = wv[i];
    }

    // ---- deterministic block partials (L2-resident) ----
    if (tid < O) {
        float s = 0.f;
#pragma unroll
        for (int r = 0; r < ROWS; r++) s += sWU[r * O + tid];
        __stcg(&g_pB[blockIdx.x][tid], s);
    } else if (tid == O) {
        float s = 0.f;
#pragma unroll
        for (int r = 0; r < ROWS; r++) s += sLD[r];
        __stcg(&g_pB[blockIdx.x][O], s);
    } else if (tid >= 32 && tid < 32 + O) {
        const int j = tid - 32;
        float s = 0.f;
#pragma unroll
        for (int r = 0; r < ROWS; r++) s += sY[r * O + j];
        __stcg(&g_pB[blockIdx.x][O + 1 + j], s);
    }

    // ---- last-block final combine ----
    __threadfence();
    __syncthreads();
    if (tid == 0) {
        const int old = atomicAdd(&g_count, 1);
        *sFlag = (old == NBLK - 1);
    }
    __syncthreads();
    if (!*sFlag) return;
    __threadfence();   // acquire all blocks' g_pB stores

    {
        float* part = sm;            // [4][PBC]
        float* tot  = sm + 4 * PBC;  // [PBC]
        const int j   = tid & 63;
        const int seg = tid >> 6;    // 4 segments x 64 blocks
        if (j < PBC) {
            float s = 0.f;
#pragma unroll
            for (int b = 0; b < NBLK / 4; b++)
                s += __ldcg(&g_pB[seg * (NBLK / 4) + b][j]);
            part[seg * PBC + j] = s;
        }
        __syncthreads();
        if (tid < PBC) {
            float s = 0.f;
#pragma unroll
            for (int sg = 0; sg < 4; sg++) s += part[sg * PBC + tid];
            tot[tid] = s;
        }
        __syncthreads();
        if (tid == 0) {
            float dot = 0.f;
#pragma unroll
            for (int jj = 0; jj < O; jj++) dot += tot[jj] * tot[O + 1 + jj];
            out[(size_t)BSZ * O] = -(dot - tot[O]);
            g_count = 0;   // reset for graph replay
        }
    }
}

// ---------------------------------------------------------------------------
extern "C" void kernel_launch(void* const* d_in, const int* in_sizes, int n_in,
                              void* d_out, int out_size) {
    const float* x  = (const float*)d_in[0];
    const float* y  = (const float*)d_in[1];
    const float* W1 = (const float*)d_in[2];
    const float* b1 = (const float*)d_in[3];
    const float* W2 = (const float*)d_in[4];
    const float* b2 = (const float*)d_in[5];
    const float* W3 = (const float*)d_in[6];
    const float* b3 = (const float*)d_in[7];
    float* out = (float*)d_out;

    cudaFuncSetAttribute(k_main, cudaFuncAttributeMaxDynamicSharedMemorySize,
                         SMEM_BYTES);

    k_main<<<NBLK, TPB, SMEM_BYTES>>>(x, y, W1, b1, W2, b2, W3, b3, out);
}